// round 9
// baseline (speedup 1.0000x reference)
#include <cuda_runtime.h>
#include <cuda_bf16.h>
#include <cstdint>

#define B_SZ 32
#define T_SZ 2048
#define DIN  1024
#define HID  2048
#define BM   128
#define BN   128
#define BK   32          // fp32 elements per K-chunk (128B rows -> SW128)
#define NCHUNK (DIN / BK)

// ---------------- device-global scratch (allocation-free) ----------------
__device__ __align__(16) float g_w132[(size_t)HID * DIN];          // 8 MB (tf32-rounded W1)
__device__ float g_part[(size_t)16 * B_SZ * HID];                  // 4 MB [tt][b][n]

// ---------------- helpers ----------------
__device__ __forceinline__ uint32_t smem_u32(const void* p) {
    uint32_t a;
    asm("{ .reg .u64 t; cvta.to.shared.u64 t, %1; cvt.u32.u64 %0, t; }" : "=r"(a) : "l"(p));
    return a;
}
__device__ __forceinline__ void ldsm_x4(uint32_t& r0, uint32_t& r1, uint32_t& r2, uint32_t& r3,
                                        uint32_t addr) {
    asm volatile("ldmatrix.sync.aligned.m8n8.x4.shared.b16 {%0,%1,%2,%3}, [%4];"
                 : "=r"(r0), "=r"(r1), "=r"(r2), "=r"(r3) : "r"(addr));
}
__device__ __forceinline__ float f2tf32f(float x) {
    uint32_t d;
    asm("cvt.rna.tf32.f32 %0, %1;" : "=r"(d) : "f"(x));
    return __uint_as_float(d);
}
__device__ __forceinline__ uint32_t f2tf32u(uint32_t bits) {
    uint32_t d;
    asm("cvt.rna.tf32.f32 %0, %1;" : "=r"(d) : "f"(__uint_as_float(bits)));
    return d;
}
__device__ __forceinline__ void mma_tf32(float* c, const uint32_t* a, const uint32_t* b) {
    asm volatile(
        "mma.sync.aligned.m16n8k8.row.col.f32.tf32.tf32.f32 "
        "{%0,%1,%2,%3}, {%4,%5,%6,%7}, {%8,%9}, {%0,%1,%2,%3};"
        : "+f"(c[0]), "+f"(c[1]), "+f"(c[2]), "+f"(c[3])
        : "r"(a[0]), "r"(a[1]), "r"(a[2]), "r"(a[3]), "r"(b[0]), "r"(b[1]));
}
#define CP_ASYNC16(dst, src) \
    asm volatile("cp.async.cg.shared.global [%0], [%1], 16;" :: "r"(dst), "l"(src))
#define CP_COMMIT() asm volatile("cp.async.commit_group;" ::: "memory")
#define CP_WAIT1()  asm volatile("cp.async.wait_group 1;" ::: "memory")

// ---------------- prepass: round W1 to tf32-representable fp32 (8MB, ~6us) ----------------
__global__ void __launch_bounds__(256) rnd_w1_kernel(const float4* __restrict__ src) {
    unsigned g = blockIdx.x * 256u + threadIdx.x;
    float4 v = src[g];
    v.x = f2tf32f(v.x); v.y = f2tf32f(v.y); v.z = f2tf32f(v.z); v.w = f2tf32f(v.w);
    reinterpret_cast<float4*>(g_w132)[g] = v;
}

// ---------------- chunk loader: 128 rows x 32 fp32 (128B/row), SW128 swizzle ----------------
__device__ __forceinline__ void load_chunk(uint32_t smA, uint32_t smB,
                                           const float* gA, const float* gB,
                                           int k0, int tid) {
#pragma unroll
    for (int j = 0; j < 4; j++) {
        int idx = tid + j * 256;
        int row = idx >> 3, seg = idx & 7;
        uint32_t sw = (uint32_t)(row * 128) + (((uint32_t)seg * 16) ^ (((uint32_t)row & 7) << 4));
        CP_ASYNC16(smA + sw, gA + (size_t)row * DIN + k0 + seg * 4);
    }
#pragma unroll
    for (int j = 0; j < 4; j++) {
        int idx = tid + j * 256;
        int row = idx >> 3, seg = idx & 7;
        uint32_t sw = (uint32_t)(row * 128) + (((uint32_t)seg * 16) ^ (((uint32_t)row & 7) << 4));
        CP_ASYNC16(smB + sw, gB + (size_t)row * DIN + k0 + seg * 4);
    }
}

// ---------------- SMEM layout ----------------
#define SM_B1   0        // 128 floats (512B)
#define SM_PART 512      // 4 x 128 floats (2KB)
#define SM_BUFA 4096     // 3 stages x 16KB
#define SM_BUFB 53248    // 3 stages x 16KB
#define SMEM_TOTAL 102400

// ---------------- fused GEMM tile (relu(h@W1^T+b1)) + column partial sums ----------------
// grid: (16 nt, 16 tt, 32 b); 256 threads; warps 4(M)x2(N), warp tile 32x64
// Pipeline: ONE barrier per chunk with distance-2 prefetch:
//   wait_group 1 -> sync -> issue loads(c+2)+commit -> compute(c)
// Safety: loads(c+2) target buf[(c+2)%3] == buf[(c-1)%3]; its readers (compute(c-1))
// all passed this iteration's barrier. Always-commit keeps group k == chunk k, so
// wait_group 1 guarantees chunk c is resident while c+1, c+2 stay in flight.
__global__ void __launch_bounds__(256, 2) gemm_kernel(const float* __restrict__ h,
                                                      const int* __restrict__ tl,
                                                      const float* __restrict__ b1) {
    const int nt = blockIdx.x, tt = blockIdx.y, b = blockIdx.z;
    const int len = tl[b];
    if (tt * BM >= len) return;

    extern __shared__ char smem[];
    float* sb1  = (float*)(smem + SM_B1);
    float* part = (float*)(smem + SM_PART);
    const uint32_t sbase = smem_u32(smem);
    const uint32_t smA = sbase + SM_BUFA;
    const uint32_t smB = sbase + SM_BUFB;

    const int tid = threadIdx.x, lane = tid & 31, wid = tid >> 5;
    const int wm = wid >> 1, wn = wid & 1;

    if (tid < 128) sb1[tid] = b1[nt * BN + tid];

    const float* gA = h      + ((size_t)b * T_SZ + (size_t)tt * BM) * DIN;
    const float* gB = g_w132 + (size_t)nt * BN * DIN;

    float acc[2][8][4];
#pragma unroll
    for (int i = 0; i < 2; i++)
#pragma unroll
        for (int j = 0; j < 8; j++)
#pragma unroll
            for (int k = 0; k < 4; k++) acc[i][j][k] = 0.f;

    // ldmatrix-as-tf32 addressing: each 8x8 b16 matrix = 8 rows x 4 fp32
    const int r8   = lane & 7;
    const uint32_t xorv = (uint32_t)r8 << 4;
    const uint32_t aColSel = ((lane >> 4) & 1) * 16;   // A: mats 2,3 -> cols +4 fp32
    const uint32_t bColSel = ((lane >> 3) & 1) * 16;   // B: mats 1,3 -> k +4
    uint32_t aRowOff[2], bRowOff[4];
#pragma unroll
    for (int mt = 0; mt < 2; mt++)
        aRowOff[mt] = (uint32_t)((wm * 32 + mt * 16 + ((lane >> 3) & 1) * 8 + r8) * 128);
#pragma unroll
    for (int p = 0; p < 4; p++)
        bRowOff[p] = (uint32_t)((wn * 64 + p * 16 + ((lane >> 4) & 1) * 8 + r8) * 128);

    // prologue: chunks 0,1 in flight
    load_chunk(smA, smB, gA, gB, 0, tid);
    CP_COMMIT();
    load_chunk(smA + 16384, smB + 16384, gA, gB, BK, tid);
    CP_COMMIT();

    for (int c = 0; c < NCHUNK; c++) {
        CP_WAIT1();              // chunk c resident (only chunk c+1's group may be open)
        __syncthreads();         // single barrier per chunk

        if (c + 2 < NCHUNK)      // prefetch distance 2, issued before compute
            load_chunk(smA + ((c + 2) % 3) * 16384, smB + ((c + 2) % 3) * 16384,
                       gA, gB, (c + 2) * BK, tid);
        CP_COMMIT();             // uniform group count (possibly empty)

        const uint32_t bufA = smA + (c % 3) * 16384;
        const uint32_t bufB = smB + (c % 3) * 16384;
#pragma unroll
        for (int ks = 0; ks < 4; ks++) {
            const uint32_t kb = (uint32_t)ks * 32;
            uint32_t a[2][4];
#pragma unroll
            for (int mt = 0; mt < 2; mt++) {
                ldsm_x4(a[mt][0], a[mt][1], a[mt][2], a[mt][3],
                        bufA + aRowOff[mt] + ((kb + aColSel) ^ xorv));
                a[mt][0] = f2tf32u(a[mt][0]); a[mt][1] = f2tf32u(a[mt][1]);
                a[mt][2] = f2tf32u(a[mt][2]); a[mt][3] = f2tf32u(a[mt][3]);
            }
#pragma unroll
            for (int p = 0; p < 4; p++) {
                uint32_t q0, q1, q2, q3;
                ldsm_x4(q0, q1, q2, q3, bufB + bRowOff[p] + ((kb + bColSel) ^ xorv));
                uint32_t bfa[2] = { q0, q1 };
                uint32_t bfb[2] = { q2, q3 };
#pragma unroll
                for (int mt = 0; mt < 2; mt++) {
                    mma_tf32(acc[mt][2 * p],     a[mt], bfa);
                    mma_tf32(acc[mt][2 * p + 1], a[mt], bfb);
                }
            }
        }
    }

    // ---- epilogue: bias + relu + row mask + deterministic column reduce ----
    const int r0g = tt * BM + wm * 32 + (lane >> 2);
#pragma unroll
    for (int n8 = 0; n8 < 8; n8++) {
        const int c0 = wn * 64 + n8 * 8 + (lane & 3) * 2;
        const float bias0 = sb1[c0], bias1 = sb1[c0 + 1];
        float s0 = 0.f, s1 = 0.f;
#pragma unroll
        for (int mt = 0; mt < 2; mt++) {
            const int rr = r0g + mt * 16;
            if (rr < len) {
                s0 += fmaxf(acc[mt][n8][0] + bias0, 0.f);
                s1 += fmaxf(acc[mt][n8][1] + bias1, 0.f);
            }
            if (rr + 8 < len) {
                s0 += fmaxf(acc[mt][n8][2] + bias0, 0.f);
                s1 += fmaxf(acc[mt][n8][3] + bias1, 0.f);
            }
        }
#pragma unroll
        for (int o = 4; o < 32; o <<= 1) {
            s0 += __shfl_xor_sync(0xffffffffu, s0, o);
            s1 += __shfl_xor_sync(0xffffffffu, s1, o);
        }
        if (lane < 4) {
            part[wm * 128 + c0] = s0;
            part[wm * 128 + c0 + 1] = s1;
        }
    }
    __syncthreads();
    if (tid < 128) {
        float v = part[tid] + part[128 + tid] + part[256 + tid] + part[384 + tid];
        g_part[((size_t)tt * B_SZ + b) * HID + nt * BN + tid] = v;
    }
}

// ---------------- fused pool-reduce + score: one block per batch ----------------
__global__ void __launch_bounds__(256) pool_score_kernel(const int* __restrict__ tl,
                                                         const float* __restrict__ W2,
                                                         const float* __restrict__ b2,
                                                         float* __restrict__ out) {
    __shared__ float red[16];  // 8 warps x 2 tags
    const int b = blockIdx.x, tid = threadIdx.x, lane = tid & 31, wid = tid >> 5;
    const int len = tl[b];
    const int ntt = (len + BM - 1) >> 7;
    const float inv = 1.f / (float)len;

    float s0 = 0.f, s1 = 0.f;
    for (int hcol = tid; hcol < HID; hcol += 256) {
        float s = 0.f;
        for (int t = 0; t < ntt; t++)
            s += g_part[((size_t)t * B_SZ + b) * HID + hcol];
        float v = s * inv;
        s0 += v * W2[hcol];
        s1 += v * W2[HID + hcol];
    }
#pragma unroll
    for (int o = 16; o > 0; o >>= 1) {
        s0 += __shfl_xor_sync(0xffffffffu, s0, o);
        s1 += __shfl_xor_sync(0xffffffffu, s1, o);
    }
    if (lane == 0) { red[wid * 2] = s0; red[wid * 2 + 1] = s1; }
    __syncthreads();
    if (tid < 2) {
        float t = 0.f;
#pragma unroll
        for (int w = 0; w < 8; w++) t += red[w * 2 + tid];
        out[b * 2 + tid] = t + b2[tid];
    }
}

// ---------------- launch ----------------
extern "C" void kernel_launch(void* const* d_in, const int* in_sizes, int n_in,
                              void* d_out, int out_size) {
    const float* h  = (const float*)d_in[0];
    const int*   tl = (const int*)d_in[1];
    const float* W1 = (const float*)d_in[2];
    const float* b1 = (const float*)d_in[3];
    const float* W2 = (const float*)d_in[4];
    const float* b2 = (const float*)d_in[5];
    float* out = (float*)d_out;

    static bool attr_set = false;
    if (!attr_set) {
        cudaFuncSetAttribute(gemm_kernel,
                             cudaFuncAttributeMaxDynamicSharedMemorySize, SMEM_TOTAL);
        attr_set = true;
    }

    rnd_w1_kernel<<<(HID * DIN / 4) / 256, 256>>>((const float4*)W1);
    gemm_kernel<<<dim3(HID / BN, T_SZ / BM, B_SZ), 256, SMEM_TOTAL>>>(h, tl, b1);
    pool_score_kernel<<<B_SZ, 256>>>(tl, W2, b2, out);
}

// round 10
// speedup vs baseline: 1.0577x; 1.0577x over previous
#include <cuda_runtime.h>
#include <cuda_bf16.h>
#include <cstdint>

#define B_SZ 32
#define T_SZ 2048
#define DIN  1024
#define HID  2048
#define BM   128
#define BN   128
#define BK   32          // fp32 elements per K-chunk (128B rows -> SW128)
#define NCHUNK (DIN / BK)

// ---------------- device-global scratch (allocation-free) ----------------
__device__ __align__(16) float g_w132[(size_t)HID * DIN];          // 8 MB (tf32-rounded W1)
__device__ float g_part[(size_t)16 * B_SZ * HID];                  // 4 MB [tt][b][n]

// ---------------- helpers ----------------
__device__ __forceinline__ uint32_t smem_u32(const void* p) {
    uint32_t a;
    asm("{ .reg .u64 t; cvta.to.shared.u64 t, %1; cvt.u32.u64 %0, t; }" : "=r"(a) : "l"(p));
    return a;
}
__device__ __forceinline__ void ldsm_x4(uint32_t& r0, uint32_t& r1, uint32_t& r2, uint32_t& r3,
                                        uint32_t addr) {
    asm volatile("ldmatrix.sync.aligned.m8n8.x4.shared.b16 {%0,%1,%2,%3}, [%4];"
                 : "=r"(r0), "=r"(r1), "=r"(r2), "=r"(r3) : "r"(addr));
}
__device__ __forceinline__ float f2tf32f(float x) {
    uint32_t d;
    asm("cvt.rna.tf32.f32 %0, %1;" : "=r"(d) : "f"(x));
    return __uint_as_float(d);
}
__device__ __forceinline__ uint32_t f2tf32u(uint32_t bits) {
    uint32_t d;
    asm("cvt.rna.tf32.f32 %0, %1;" : "=r"(d) : "f"(__uint_as_float(bits)));
    return d;
}
__device__ __forceinline__ void mma_tf32(float* c, const uint32_t* a, const uint32_t* b) {
    asm volatile(
        "mma.sync.aligned.m16n8k8.row.col.f32.tf32.tf32.f32 "
        "{%0,%1,%2,%3}, {%4,%5,%6,%7}, {%8,%9}, {%0,%1,%2,%3};"
        : "+f"(c[0]), "+f"(c[1]), "+f"(c[2]), "+f"(c[3])
        : "r"(a[0]), "r"(a[1]), "r"(a[2]), "r"(a[3]), "r"(b[0]), "r"(b[1]));
}
#define CP_ASYNC16(dst, src) \
    asm volatile("cp.async.cg.shared.global [%0], [%1], 16;" :: "r"(dst), "l"(src))
#define CP_COMMIT() asm volatile("cp.async.commit_group;" ::: "memory")
#define CP_WAIT2()  asm volatile("cp.async.wait_group 2;" ::: "memory")

// ---------------- prepass: round W1 to tf32-representable fp32 (8MB) ----------------
__global__ void __launch_bounds__(256) rnd_w1_kernel(const float4* __restrict__ src) {
    unsigned g = blockIdx.x * 256u + threadIdx.x;   // each thread: 2 float4 (MLP=2)
    float4 v0 = src[g * 2], v1 = src[g * 2 + 1];
    v0.x = f2tf32f(v0.x); v0.y = f2tf32f(v0.y); v0.z = f2tf32f(v0.z); v0.w = f2tf32f(v0.w);
    v1.x = f2tf32f(v1.x); v1.y = f2tf32f(v1.y); v1.z = f2tf32f(v1.z); v1.w = f2tf32f(v1.w);
    reinterpret_cast<float4*>(g_w132)[g * 2]     = v0;
    reinterpret_cast<float4*>(g_w132)[g * 2 + 1] = v1;
}

// ---------------- chunk loader: 128 rows x 32 fp32 (128B/row), SW128 swizzle ----------------
__device__ __forceinline__ void load_chunk(uint32_t smA, uint32_t smB,
                                           const float* gA, const float* gB,
                                           int k0, int tid) {
#pragma unroll
    for (int j = 0; j < 4; j++) {
        int idx = tid + j * 256;
        int row = idx >> 3, seg = idx & 7;
        uint32_t sw = (uint32_t)(row * 128) + (((uint32_t)seg * 16) ^ (((uint32_t)row & 7) << 4));
        CP_ASYNC16(smA + sw, gA + (size_t)row * DIN + k0 + seg * 4);
    }
#pragma unroll
    for (int j = 0; j < 4; j++) {
        int idx = tid + j * 256;
        int row = idx >> 3, seg = idx & 7;
        uint32_t sw = (uint32_t)(row * 128) + (((uint32_t)seg * 16) ^ (((uint32_t)row & 7) << 4));
        CP_ASYNC16(smB + sw, gB + (size_t)row * DIN + k0 + seg * 4);
    }
}

// ---------------- SMEM layout ----------------
#define SM_B1   0        // 128 floats (512B)
#define SM_PART 512      // 4 x 128 floats (2KB)
#define SM_BUFA 4096     // 3 stages x 16KB
#define SM_BUFB 53248    // 3 stages x 16KB
#define SMEM_TOTAL 102400

// ---------------- fused GEMM tile (relu(h@W1^T+b1)) + column partial sums ----------------
// R6-proven pipeline: loads at top (overlap barrier skew), distance-2 prefetch,
// wait2 -> sync -> compute -> sync. In-loop rna cvts on A fragments (R6 numerics).
__global__ void __launch_bounds__(256, 2) gemm_kernel(const float* __restrict__ h,
                                                      const int* __restrict__ tl,
                                                      const float* __restrict__ b1) {
    const int nt = blockIdx.x, tt = blockIdx.y, b = blockIdx.z;
    const int len = tl[b];
    if (tt * BM >= len) return;

    extern __shared__ char smem[];
    float* sb1  = (float*)(smem + SM_B1);
    float* part = (float*)(smem + SM_PART);
    const uint32_t sbase = smem_u32(smem);
    const uint32_t smA = sbase + SM_BUFA;
    const uint32_t smB = sbase + SM_BUFB;

    const int tid = threadIdx.x, lane = tid & 31, wid = tid >> 5;
    const int wm = wid >> 1, wn = wid & 1;

    if (tid < 128) sb1[tid] = b1[nt * BN + tid];

    const float* gA = h      + ((size_t)b * T_SZ + (size_t)tt * BM) * DIN;
    const float* gB = g_w132 + (size_t)nt * BN * DIN;

    float acc[2][8][4];
#pragma unroll
    for (int i = 0; i < 2; i++)
#pragma unroll
        for (int j = 0; j < 8; j++)
#pragma unroll
            for (int k = 0; k < 4; k++) acc[i][j][k] = 0.f;

    // ldmatrix-as-tf32 addressing: each 8x8 b16 matrix = 8 rows x 4 fp32
    const int r8   = lane & 7;
    const uint32_t xorv = (uint32_t)r8 << 4;
    const uint32_t aColSel = ((lane >> 4) & 1) * 16;   // A: mats 2,3 -> cols +4 fp32
    const uint32_t bColSel = ((lane >> 3) & 1) * 16;   // B: mats 1,3 -> k +4
    uint32_t aRowOff[2], bRowOff[4];
#pragma unroll
    for (int mt = 0; mt < 2; mt++)
        aRowOff[mt] = (uint32_t)((wm * 32 + mt * 16 + ((lane >> 3) & 1) * 8 + r8) * 128);
#pragma unroll
    for (int p = 0; p < 4; p++)
        bRowOff[p] = (uint32_t)((wn * 64 + p * 16 + ((lane >> 4) & 1) * 8 + r8) * 128);

    // 3-stage cp.async pipeline, prefetch distance 2
    load_chunk(smA, smB, gA, gB, 0, tid);
    CP_COMMIT();
    load_chunk(smA + 16384, smB + 16384, gA, gB, BK, tid);
    CP_COMMIT();

    for (int c = 0; c < NCHUNK; c++) {
        if (c + 2 < NCHUNK)
            load_chunk(smA + ((c + 2) % 3) * 16384, smB + ((c + 2) % 3) * 16384,
                       gA, gB, (c + 2) * BK, tid);
        CP_COMMIT();          // uniform group count (possibly empty)
        CP_WAIT2();
        __syncthreads();

        const uint32_t bufA = smA + (c % 3) * 16384;
        const uint32_t bufB = smB + (c % 3) * 16384;
#pragma unroll
        for (int ks = 0; ks < 4; ks++) {
            const uint32_t kb = (uint32_t)ks * 32;
            uint32_t a[2][4];
#pragma unroll
            for (int mt = 0; mt < 2; mt++) {
                ldsm_x4(a[mt][0], a[mt][1], a[mt][2], a[mt][3],
                        bufA + aRowOff[mt] + ((kb + aColSel) ^ xorv));
                a[mt][0] = f2tf32u(a[mt][0]); a[mt][1] = f2tf32u(a[mt][1]);
                a[mt][2] = f2tf32u(a[mt][2]); a[mt][3] = f2tf32u(a[mt][3]);
            }
#pragma unroll
            for (int p = 0; p < 4; p++) {
                uint32_t q0, q1, q2, q3;
                ldsm_x4(q0, q1, q2, q3, bufB + bRowOff[p] + ((kb + bColSel) ^ xorv));
                uint32_t bfa[2] = { q0, q1 };
                uint32_t bfb[2] = { q2, q3 };
#pragma unroll
                for (int mt = 0; mt < 2; mt++) {
                    mma_tf32(acc[mt][2 * p],     a[mt], bfa);
                    mma_tf32(acc[mt][2 * p + 1], a[mt], bfb);
                }
            }
        }
        __syncthreads();
    }

    // ---- epilogue: bias + relu + row mask + deterministic column reduce ----
    const int r0g = tt * BM + wm * 32 + (lane >> 2);
#pragma unroll
    for (int n8 = 0; n8 < 8; n8++) {
        const int c0 = wn * 64 + n8 * 8 + (lane & 3) * 2;
        const float bias0 = sb1[c0], bias1 = sb1[c0 + 1];
        float s0 = 0.f, s1 = 0.f;
#pragma unroll
        for (int mt = 0; mt < 2; mt++) {
            const int rr = r0g + mt * 16;
            if (rr < len) {
                s0 += fmaxf(acc[mt][n8][0] + bias0, 0.f);
                s1 += fmaxf(acc[mt][n8][1] + bias1, 0.f);
            }
            if (rr + 8 < len) {
                s0 += fmaxf(acc[mt][n8][2] + bias0, 0.f);
                s1 += fmaxf(acc[mt][n8][3] + bias1, 0.f);
            }
        }
#pragma unroll
        for (int o = 4; o < 32; o <<= 1) {
            s0 += __shfl_xor_sync(0xffffffffu, s0, o);
            s1 += __shfl_xor_sync(0xffffffffu, s1, o);
        }
        if (lane < 4) {
            part[wm * 128 + c0] = s0;
            part[wm * 128 + c0 + 1] = s1;
        }
    }
    __syncthreads();
    if (tid < 128) {
        float v = part[tid] + part[128 + tid] + part[256 + tid] + part[384 + tid];
        g_part[((size_t)tt * B_SZ + b) * HID + nt * BN + tid] = v;
    }
}

// ---------------- fused pool-reduce + score: one block per batch ----------------
__global__ void __launch_bounds__(256) pool_score_kernel(const int* __restrict__ tl,
                                                         const float* __restrict__ W2,
                                                         const float* __restrict__ b2,
                                                         float* __restrict__ out) {
    __shared__ float red[16];  // 8 warps x 2 tags
    const int b = blockIdx.x, tid = threadIdx.x, lane = tid & 31, wid = tid >> 5;
    const int len = tl[b];
    const int ntt = (len + BM - 1) >> 7;
    const float inv = 1.f / (float)len;

    float s0 = 0.f, s1 = 0.f;
    for (int hcol = tid; hcol < HID; hcol += 256) {
        float s = 0.f;
        for (int t = 0; t < ntt; t++)
            s += g_part[((size_t)t * B_SZ + b) * HID + hcol];
        float v = s * inv;
        s0 += v * W2[hcol];
        s1 += v * W2[HID + hcol];
    }
#pragma unroll
    for (int o = 16; o > 0; o >>= 1) {
        s0 += __shfl_xor_sync(0xffffffffu, s0, o);
        s1 += __shfl_xor_sync(0xffffffffu, s1, o);
    }
    if (lane == 0) { red[wid * 2] = s0; red[wid * 2 + 1] = s1; }
    __syncthreads();
    if (tid < 2) {
        float t = 0.f;
#pragma unroll
        for (int w = 0; w < 8; w++) t += red[w * 2 + tid];
        out[b * 2 + tid] = t + b2[tid];
    }
}

// ---------------- launch ----------------
extern "C" void kernel_launch(void* const* d_in, const int* in_sizes, int n_in,
                              void* d_out, int out_size) {
    const float* h  = (const float*)d_in[0];
    const int*   tl = (const int*)d_in[1];
    const float* W1 = (const float*)d_in[2];
    const float* b1 = (const float*)d_in[3];
    const float* W2 = (const float*)d_in[4];
    const float* b2 = (const float*)d_in[5];
    float* out = (float*)d_out;

    static bool attr_set = false;
    if (!attr_set) {
        cudaFuncSetAttribute(gemm_kernel,
                             cudaFuncAttributeMaxDynamicSharedMemorySize, SMEM_TOTAL);
        attr_set = true;
    }

    rnd_w1_kernel<<<(HID * DIN / 8) / 256, 256>>>((const float4*)W1);
    gemm_kernel<<<dim3(HID / BN, T_SZ / BM, B_SZ), 256, SMEM_TOTAL>>>(h, tl, b1);
    pool_score_kernel<<<B_SZ, 256>>>(tl, W2, b2, out);
}

// round 11
// speedup vs baseline: 1.7921x; 1.6943x over previous
#include <cuda_runtime.h>
#include <cuda_fp16.h>
#include <cstdint>

#define B_SZ 32
#define T_SZ 2048
#define DIN  1024
#define HID  2048
#define BM   128
#define BN   128
#define BK   64          // fp16 elements per K-chunk (128B rows -> SW128)
#define NCHUNK (DIN / BK)

// ---------------- device-global scratch (allocation-free) ----------------
__device__ __align__(16) __half g_h16 [(size_t)B_SZ * T_SZ * DIN];  // 128 MB
__device__ __align__(16) __half g_w116[(size_t)HID * DIN];           // 4 MB
__device__ float g_part[(size_t)16 * B_SZ * HID];                    // 4 MB [tt][b][n]

// ---------------- helpers ----------------
__device__ __forceinline__ uint32_t smem_u32(const void* p) {
    uint32_t a;
    asm("{ .reg .u64 t; cvta.to.shared.u64 t, %1; cvt.u32.u64 %0, t; }" : "=r"(a) : "l"(p));
    return a;
}
__device__ __forceinline__ void ldsm_x4(uint32_t& r0, uint32_t& r1, uint32_t& r2, uint32_t& r3,
                                        uint32_t addr) {
    asm volatile("ldmatrix.sync.aligned.m8n8.x4.shared.b16 {%0,%1,%2,%3}, [%4];"
                 : "=r"(r0), "=r"(r1), "=r"(r2), "=r"(r3) : "r"(addr));
}
__device__ __forceinline__ void mma_f16(float* c, const uint32_t* a, const uint32_t* b) {
    asm volatile(
        "mma.sync.aligned.m16n8k16.row.col.f32.f16.f16.f32 "
        "{%0,%1,%2,%3}, {%4,%5,%6,%7}, {%8,%9}, {%0,%1,%2,%3};"
        : "+f"(c[0]), "+f"(c[1]), "+f"(c[2]), "+f"(c[3])
        : "r"(a[0]), "r"(a[1]), "r"(a[2]), "r"(a[3]), "r"(b[0]), "r"(b[1]));
}
#define CP_ASYNC16(dst, src) \
    asm volatile("cp.async.cg.shared.global [%0], [%1], 16;" :: "r"(dst), "l"(src))
#define CP_COMMIT() asm volatile("cp.async.commit_group;" ::: "memory")
#define CP_WAIT2()  asm volatile("cp.async.wait_group 2;" ::: "memory")

// ---------------- conversion kernels (fp32 -> fp16 RNE) ----------------
__global__ void __launch_bounds__(256) cvt_h_kernel(const float4* __restrict__ src,
                                                    const int* __restrict__ tl) {
    unsigned g = blockIdx.x * 256u + threadIdx.x;       // one group = 8 floats
    unsigned b = g >> 18;                               // 262144 groups per batch
    unsigned t = (g >> 7) & (T_SZ - 1);                 // 128 groups per t-row
    int len = tl[b];
    unsigned tmax = ((unsigned)len + 127u) & ~127u;     // only rows the GEMM reads
    if (t >= tmax) return;
    float4 a = src[(size_t)g * 2], c = src[(size_t)g * 2 + 1];
    __half2 r0 = __floats2half2_rn(a.x, a.y);
    __half2 r1 = __floats2half2_rn(a.z, a.w);
    __half2 r2 = __floats2half2_rn(c.x, c.y);
    __half2 r3 = __floats2half2_rn(c.z, c.w);
    uint4 u;
    u.x = *reinterpret_cast<uint32_t*>(&r0);
    u.y = *reinterpret_cast<uint32_t*>(&r1);
    u.z = *reinterpret_cast<uint32_t*>(&r2);
    u.w = *reinterpret_cast<uint32_t*>(&r3);
    reinterpret_cast<uint4*>(g_h16)[g] = u;
}

__global__ void __launch_bounds__(256) cvt_w1_kernel(const float4* __restrict__ src) {
    unsigned g = blockIdx.x * 256u + threadIdx.x;
    float4 a = src[(size_t)g * 2], c = src[(size_t)g * 2 + 1];
    __half2 r0 = __floats2half2_rn(a.x, a.y);
    __half2 r1 = __floats2half2_rn(a.z, a.w);
    __half2 r2 = __floats2half2_rn(c.x, c.y);
    __half2 r3 = __floats2half2_rn(c.z, c.w);
    uint4 u;
    u.x = *reinterpret_cast<uint32_t*>(&r0);
    u.y = *reinterpret_cast<uint32_t*>(&r1);
    u.z = *reinterpret_cast<uint32_t*>(&r2);
    u.w = *reinterpret_cast<uint32_t*>(&r3);
    reinterpret_cast<uint4*>(g_w116)[g] = u;
}

// ---------------- chunk loader: 128 rows x 64 fp16 (128B/row), SW128 swizzle ----------------
__device__ __forceinline__ void load_chunk(uint32_t smA, uint32_t smB,
                                           const __half* gA, const __half* gB,
                                           int k0, int tid) {
#pragma unroll
    for (int j = 0; j < 4; j++) {
        int idx = tid + j * 256;
        int row = idx >> 3, seg = idx & 7;
        uint32_t sw = (uint32_t)(row * 128) + (((uint32_t)seg * 16) ^ (((uint32_t)row & 7) << 4));
        CP_ASYNC16(smA + sw, (const char*)(gA + (size_t)row * DIN + k0) + seg * 16);
    }
#pragma unroll
    for (int j = 0; j < 4; j++) {
        int idx = tid + j * 256;
        int row = idx >> 3, seg = idx & 7;
        uint32_t sw = (uint32_t)(row * 128) + (((uint32_t)seg * 16) ^ (((uint32_t)row & 7) << 4));
        CP_ASYNC16(smB + sw, (const char*)(gB + (size_t)row * DIN + k0) + seg * 16);
    }
}

// ---------------- SMEM layout ----------------
#define SM_B1   0        // 128 floats (512B)
#define SM_PART 512      // 4 x 128 floats (2KB)
#define SM_BUFA 4096     // 3 stages x 16KB
#define SM_BUFB 53248    // 3 stages x 16KB
#define SMEM_TOTAL 102400

// ---------------- fused GEMM tile (relu(h@W1^T+b1)) + column partial sums ----------------
// grid: (16 nt, 16 tt, 32 b); 256 threads; warps 4(M)x2(N), warp tile 32x64
// fp16 operands (same 10-bit mantissa as tf32), fp32 accumulate, m16n8k16.
// R6-proven pipeline: loads at top, distance-2 prefetch, wait2 -> sync -> compute -> sync.
__global__ void __launch_bounds__(256, 2) gemm_kernel(const int* __restrict__ tl,
                                                      const float* __restrict__ b1) {
    const int nt = blockIdx.x, tt = blockIdx.y, b = blockIdx.z;
    const int len = tl[b];
    if (tt * BM >= len) return;

    extern __shared__ char smem[];
    float* sb1  = (float*)(smem + SM_B1);
    float* part = (float*)(smem + SM_PART);
    const uint32_t sbase = smem_u32(smem);
    const uint32_t smA = sbase + SM_BUFA;
    const uint32_t smB = sbase + SM_BUFB;

    const int tid = threadIdx.x, lane = tid & 31, wid = tid >> 5;
    const int wm = wid >> 1, wn = wid & 1;

    if (tid < 128) sb1[tid] = b1[nt * BN + tid];

    const __half* gA = g_h16  + ((size_t)b * T_SZ + (size_t)tt * BM) * DIN;
    const __half* gB = g_w116 + (size_t)nt * BN * DIN;

    float acc[2][8][4];
#pragma unroll
    for (int i = 0; i < 2; i++)
#pragma unroll
        for (int j = 0; j < 8; j++)
#pragma unroll
            for (int k = 0; k < 4; k++) acc[i][j][k] = 0.f;

    // ldmatrix addressing (b16): A frag = m16xk16 per ldsm.x4, B frag = n16xk16
    const int r8  = lane & 7;
    const int mi  = lane >> 3;
    const uint32_t rot = (uint32_t)r8 << 4;
    const uint32_t akx = (uint32_t)(mi >> 1) * 16;   // A: mats 2,3 -> k+8 halves
    const uint32_t bkx = (uint32_t)(mi & 1) * 16;    // B: mats 1,3 -> k+8
    uint32_t aRow[2], bRow[4];
#pragma unroll
    for (int mt = 0; mt < 2; mt++)
        aRow[mt] = (uint32_t)((wm * 32 + mt * 16 + (mi & 1) * 8 + r8) * 128);
#pragma unroll
    for (int p = 0; p < 4; p++)
        bRow[p] = (uint32_t)((wn * 64 + p * 16 + (mi >> 1) * 8 + r8) * 128);

    // 3-stage cp.async pipeline, prefetch distance 2
    load_chunk(smA, smB, gA, gB, 0, tid);
    CP_COMMIT();
    load_chunk(smA + 16384, smB + 16384, gA, gB, BK, tid);
    CP_COMMIT();

    for (int c = 0; c < NCHUNK; c++) {
        if (c + 2 < NCHUNK)
            load_chunk(smA + ((c + 2) % 3) * 16384, smB + ((c + 2) % 3) * 16384,
                       gA, gB, (c + 2) * BK, tid);
        CP_COMMIT();          // uniform group count (possibly empty)
        CP_WAIT2();
        __syncthreads();

        const uint32_t bufA = smA + (c % 3) * 16384;
        const uint32_t bufB = smB + (c % 3) * 16384;
#pragma unroll
        for (int ks = 0; ks < 4; ks++) {          // 4 x k16 = 64
            const uint32_t kb = (uint32_t)ks * 32; // 16 halves = 32B
            uint32_t a[2][4];
#pragma unroll
            for (int mt = 0; mt < 2; mt++)
                ldsm_x4(a[mt][0], a[mt][1], a[mt][2], a[mt][3],
                        bufA + aRow[mt] + ((kb + akx) ^ rot));
#pragma unroll
            for (int p = 0; p < 4; p++) {
                uint32_t q0, q1, q2, q3;
                ldsm_x4(q0, q1, q2, q3, bufB + bRow[p] + ((kb + bkx) ^ rot));
                uint32_t bfa[2] = { q0, q1 };     // n8 tile rows +0..7
                uint32_t bfb[2] = { q2, q3 };     // n8 tile rows +8..15
#pragma unroll
                for (int mt = 0; mt < 2; mt++) {
                    mma_f16(acc[mt][2 * p],     a[mt], bfa);
                    mma_f16(acc[mt][2 * p + 1], a[mt], bfb);
                }
            }
        }
        __syncthreads();
    }

    // ---- epilogue: bias + relu + row mask + deterministic column reduce ----
    const int r0g = tt * BM + wm * 32 + (lane >> 2);
#pragma unroll
    for (int n8 = 0; n8 < 8; n8++) {
        const int c0 = wn * 64 + n8 * 8 + (lane & 3) * 2;
        const float bias0 = sb1[c0], bias1 = sb1[c0 + 1];
        float s0 = 0.f, s1 = 0.f;
#pragma unroll
        for (int mt = 0; mt < 2; mt++) {
            const int rr = r0g + mt * 16;
            if (rr < len) {
                s0 += fmaxf(acc[mt][n8][0] + bias0, 0.f);
                s1 += fmaxf(acc[mt][n8][1] + bias1, 0.f);
            }
            if (rr + 8 < len) {
                s0 += fmaxf(acc[mt][n8][2] + bias0, 0.f);
                s1 += fmaxf(acc[mt][n8][3] + bias1, 0.f);
            }
        }
#pragma unroll
        for (int o = 4; o < 32; o <<= 1) {
            s0 += __shfl_xor_sync(0xffffffffu, s0, o);
            s1 += __shfl_xor_sync(0xffffffffu, s1, o);
        }
        if (lane < 4) {
            part[wm * 128 + c0] = s0;
            part[wm * 128 + c0 + 1] = s1;
        }
    }
    __syncthreads();
    if (tid < 128) {
        float v = part[tid] + part[128 + tid] + part[256 + tid] + part[384 + tid];
        g_part[((size_t)tt * B_SZ + b) * HID + nt * BN + tid] = v;
    }
}

// ---------------- fused pool-reduce + score: one block per batch ----------------
__global__ void __launch_bounds__(256) pool_score_kernel(const int* __restrict__ tl,
                                                         const float* __restrict__ W2,
                                                         const float* __restrict__ b2,
                                                         float* __restrict__ out) {
    __shared__ float red[16];  // 8 warps x 2 tags
    const int b = blockIdx.x, tid = threadIdx.x, lane = tid & 31, wid = tid >> 5;
    const int len = tl[b];
    const int ntt = (len + BM - 1) >> 7;
    const float inv = 1.f / (float)len;

    float s0 = 0.f, s1 = 0.f;
    for (int hcol = tid; hcol < HID; hcol += 256) {
        float s = 0.f;
        for (int t = 0; t < ntt; t++)
            s += g_part[((size_t)t * B_SZ + b) * HID + hcol];
        float v = s * inv;
        s0 += v * W2[hcol];
        s1 += v * W2[HID + hcol];
    }
#pragma unroll
    for (int o = 16; o > 0; o >>= 1) {
        s0 += __shfl_xor_sync(0xffffffffu, s0, o);
        s1 += __shfl_xor_sync(0xffffffffu, s1, o);
    }
    if (lane == 0) { red[wid * 2] = s0; red[wid * 2 + 1] = s1; }
    __syncthreads();
    if (tid < 2) {
        float t = 0.f;
#pragma unroll
        for (int w = 0; w < 8; w++) t += red[w * 2 + tid];
        out[b * 2 + tid] = t + b2[tid];
    }
}

// ---------------- launch ----------------
extern "C" void kernel_launch(void* const* d_in, const int* in_sizes, int n_in,
                              void* d_out, int out_size) {
    const float* h  = (const float*)d_in[0];
    const int*   tl = (const int*)d_in[1];
    const float* W1 = (const float*)d_in[2];
    const float* b1 = (const float*)d_in[3];
    const float* W2 = (const float*)d_in[4];
    const float* b2 = (const float*)d_in[5];
    float* out = (float*)d_out;

    static bool attr_set = false;
    if (!attr_set) {
        cudaFuncSetAttribute(gemm_kernel,
                             cudaFuncAttributeMaxDynamicSharedMemorySize, SMEM_TOTAL);
        attr_set = true;
    }

    cvt_h_kernel<<<(B_SZ * T_SZ * DIN / 8) / 256, 256>>>((const float4*)h, tl);
    cvt_w1_kernel<<<(HID * DIN / 8) / 256, 256>>>((const float4*)W1);
    gemm_kernel<<<dim3(HID / BN, T_SZ / BM, B_SZ), 256, SMEM_TOTAL>>>(tl, b1);
    pool_score_kernel<<<B_SZ, 256>>>(tl, W2, b2, out);
}

// round 12
// speedup vs baseline: 1.8497x; 1.0321x over previous
#include <cuda_runtime.h>
#include <cuda_fp16.h>
#include <cstdint>

#define B_SZ 32
#define T_SZ 2048
#define DIN  1024
#define HID  2048
#define BM   128
#define BN   128
#define BK   64          // fp16 elements per K-chunk (128B rows -> SW128)
#define NCHUNK (DIN / BK)

// ---------------- device-global scratch (allocation-free) ----------------
__device__ __align__(16) __half g_h16 [(size_t)B_SZ * T_SZ * DIN];  // 128 MB
__device__ __align__(16) __half g_w116[(size_t)HID * DIN];           // 4 MB
__device__ float g_part[(size_t)16 * B_SZ * HID];                    // 4 MB [tt][b][n]
__device__ float g_red[B_SZ * 8 * 2];                                // slice partials

// ---------------- helpers ----------------
__device__ __forceinline__ uint32_t smem_u32(const void* p) {
    uint32_t a;
    asm("{ .reg .u64 t; cvta.to.shared.u64 t, %1; cvt.u32.u64 %0, t; }" : "=r"(a) : "l"(p));
    return a;
}
__device__ __forceinline__ void ldsm_x4(uint32_t& r0, uint32_t& r1, uint32_t& r2, uint32_t& r3,
                                        uint32_t addr) {
    asm volatile("ldmatrix.sync.aligned.m8n8.x4.shared.b16 {%0,%1,%2,%3}, [%4];"
                 : "=r"(r0), "=r"(r1), "=r"(r2), "=r"(r3) : "r"(addr));
}
__device__ __forceinline__ void mma_f16(float* c, const uint32_t* a, const uint32_t* b) {
    asm volatile(
        "mma.sync.aligned.m16n8k16.row.col.f32.f16.f16.f32 "
        "{%0,%1,%2,%3}, {%4,%5,%6,%7}, {%8,%9}, {%0,%1,%2,%3};"
        : "+f"(c[0]), "+f"(c[1]), "+f"(c[2]), "+f"(c[3])
        : "r"(a[0]), "r"(a[1]), "r"(a[2]), "r"(a[3]), "r"(b[0]), "r"(b[1]));
}
#define CP_ASYNC16(dst, src) \
    asm volatile("cp.async.cg.shared.global [%0], [%1], 16;" :: "r"(dst), "l"(src))
#define CP_COMMIT() asm volatile("cp.async.commit_group;" ::: "memory")
#define CP_WAIT2()  asm volatile("cp.async.wait_group 2;" ::: "memory")

// ---------------- conversion kernels (fp32 -> fp16 RNE) ----------------
__global__ void __launch_bounds__(256) cvt_h_kernel(const float4* __restrict__ src,
                                                    const int* __restrict__ tl) {
    unsigned g0 = (blockIdx.x * 256u + threadIdx.x) * 2u;   // 2 groups of 8 floats
#pragma unroll
    for (int it = 0; it < 2; it++) {
        unsigned g = g0 + it;
        unsigned b = g >> 18;                               // 262144 groups per batch
        unsigned t = (g >> 7) & (T_SZ - 1);                 // 128 groups per t-row
        int len = tl[b];
        unsigned tmax = ((unsigned)len + 127u) & ~127u;     // only rows the GEMM reads
        if (t >= tmax) continue;
        float4 a = src[(size_t)g * 2], c = src[(size_t)g * 2 + 1];
        __half2 r0 = __floats2half2_rn(a.x, a.y);
        __half2 r1 = __floats2half2_rn(a.z, a.w);
        __half2 r2 = __floats2half2_rn(c.x, c.y);
        __half2 r3 = __floats2half2_rn(c.z, c.w);
        uint4 u;
        u.x = *reinterpret_cast<uint32_t*>(&r0);
        u.y = *reinterpret_cast<uint32_t*>(&r1);
        u.z = *reinterpret_cast<uint32_t*>(&r2);
        u.w = *reinterpret_cast<uint32_t*>(&r3);
        reinterpret_cast<uint4*>(g_h16)[g] = u;
    }
}

__global__ void __launch_bounds__(256) cvt_w1_kernel(const float4* __restrict__ src) {
    unsigned g = blockIdx.x * 256u + threadIdx.x;
    float4 a = src[(size_t)g * 2], c = src[(size_t)g * 2 + 1];
    __half2 r0 = __floats2half2_rn(a.x, a.y);
    __half2 r1 = __floats2half2_rn(a.z, a.w);
    __half2 r2 = __floats2half2_rn(c.x, c.y);
    __half2 r3 = __floats2half2_rn(c.z, c.w);
    uint4 u;
    u.x = *reinterpret_cast<uint32_t*>(&r0);
    u.y = *reinterpret_cast<uint32_t*>(&r1);
    u.z = *reinterpret_cast<uint32_t*>(&r2);
    u.w = *reinterpret_cast<uint32_t*>(&r3);
    reinterpret_cast<uint4*>(g_w116)[g] = u;
}

// ---------------- chunk loader: 128 rows x 64 fp16 (128B/row), SW128 swizzle ----------------
__device__ __forceinline__ void load_chunk(uint32_t smA, uint32_t smB,
                                           const __half* gA, const __half* gB,
                                           int k0, int tid) {
#pragma unroll
    for (int j = 0; j < 4; j++) {
        int idx = tid + j * 256;
        int row = idx >> 3, seg = idx & 7;
        uint32_t sw = (uint32_t)(row * 128) + (((uint32_t)seg * 16) ^ (((uint32_t)row & 7) << 4));
        CP_ASYNC16(smA + sw, (const char*)(gA + (size_t)row * DIN + k0) + seg * 16);
    }
#pragma unroll
    for (int j = 0; j < 4; j++) {
        int idx = tid + j * 256;
        int row = idx >> 3, seg = idx & 7;
        uint32_t sw = (uint32_t)(row * 128) + (((uint32_t)seg * 16) ^ (((uint32_t)row & 7) << 4));
        CP_ASYNC16(smB + sw, (const char*)(gB + (size_t)row * DIN + k0) + seg * 16);
    }
}

// ---------------- SMEM layout ----------------
#define SM_B1   0        // 128 floats (512B)
#define SM_PART 512      // 4 x 128 floats (2KB)
#define SM_BUFA 4096     // 3 stages x 16KB
#define SM_BUFB 53248    // 3 stages x 16KB
#define SMEM_TOTAL 102400

// ---------------- fused GEMM tile (relu(h@W1^T+b1)) + column partial sums ----------------
// grid: (16 nt, 16 tt, 32 b); 256 threads; warps 4(M)x2(N), warp tile 32x64
// fp16 operands, fp32 accumulate, m16n8k16. R6-proven pipeline (UNCHANGED from R11).
__global__ void __launch_bounds__(256, 2) gemm_kernel(const int* __restrict__ tl,
                                                      const float* __restrict__ b1) {
    const int nt = blockIdx.x, tt = blockIdx.y, b = blockIdx.z;
    const int len = tl[b];
    if (tt * BM >= len) return;

    extern __shared__ char smem[];
    float* sb1  = (float*)(smem + SM_B1);
    float* part = (float*)(smem + SM_PART);
    const uint32_t sbase = smem_u32(smem);
    const uint32_t smA = sbase + SM_BUFA;
    const uint32_t smB = sbase + SM_BUFB;

    const int tid = threadIdx.x, lane = tid & 31, wid = tid >> 5;
    const int wm = wid >> 1, wn = wid & 1;

    if (tid < 128) sb1[tid] = b1[nt * BN + tid];

    const __half* gA = g_h16  + ((size_t)b * T_SZ + (size_t)tt * BM) * DIN;
    const __half* gB = g_w116 + (size_t)nt * BN * DIN;

    float acc[2][8][4];
#pragma unroll
    for (int i = 0; i < 2; i++)
#pragma unroll
        for (int j = 0; j < 8; j++)
#pragma unroll
            for (int k = 0; k < 4; k++) acc[i][j][k] = 0.f;

    const int r8  = lane & 7;
    const int mi  = lane >> 3;
    const uint32_t rot = (uint32_t)r8 << 4;
    const uint32_t akx = (uint32_t)(mi >> 1) * 16;
    const uint32_t bkx = (uint32_t)(mi & 1) * 16;
    uint32_t aRow[2], bRow[4];
#pragma unroll
    for (int mt = 0; mt < 2; mt++)
        aRow[mt] = (uint32_t)((wm * 32 + mt * 16 + (mi & 1) * 8 + r8) * 128);
#pragma unroll
    for (int p = 0; p < 4; p++)
        bRow[p] = (uint32_t)((wn * 64 + p * 16 + (mi >> 1) * 8 + r8) * 128);

    load_chunk(smA, smB, gA, gB, 0, tid);
    CP_COMMIT();
    load_chunk(smA + 16384, smB + 16384, gA, gB, BK, tid);
    CP_COMMIT();

    for (int c = 0; c < NCHUNK; c++) {
        if (c + 2 < NCHUNK)
            load_chunk(smA + ((c + 2) % 3) * 16384, smB + ((c + 2) % 3) * 16384,
                       gA, gB, (c + 2) * BK, tid);
        CP_COMMIT();
        CP_WAIT2();
        __syncthreads();

        const uint32_t bufA = smA + (c % 3) * 16384;
        const uint32_t bufB = smB + (c % 3) * 16384;
#pragma unroll
        for (int ks = 0; ks < 4; ks++) {
            const uint32_t kb = (uint32_t)ks * 32;
            uint32_t a[2][4];
#pragma unroll
            for (int mt = 0; mt < 2; mt++)
                ldsm_x4(a[mt][0], a[mt][1], a[mt][2], a[mt][3],
                        bufA + aRow[mt] + ((kb + akx) ^ rot));
#pragma unroll
            for (int p = 0; p < 4; p++) {
                uint32_t q0, q1, q2, q3;
                ldsm_x4(q0, q1, q2, q3, bufB + bRow[p] + ((kb + bkx) ^ rot));
                uint32_t bfa[2] = { q0, q1 };
                uint32_t bfb[2] = { q2, q3 };
#pragma unroll
                for (int mt = 0; mt < 2; mt++) {
                    mma_f16(acc[mt][2 * p],     a[mt], bfa);
                    mma_f16(acc[mt][2 * p + 1], a[mt], bfb);
                }
            }
        }
        __syncthreads();
    }

    // ---- epilogue: bias + relu + row mask + deterministic column reduce ----
    const int r0g = tt * BM + wm * 32 + (lane >> 2);
#pragma unroll
    for (int n8 = 0; n8 < 8; n8++) {
        const int c0 = wn * 64 + n8 * 8 + (lane & 3) * 2;
        const float bias0 = sb1[c0], bias1 = sb1[c0 + 1];
        float s0 = 0.f, s1 = 0.f;
#pragma unroll
        for (int mt = 0; mt < 2; mt++) {
            const int rr = r0g + mt * 16;
            if (rr < len) {
                s0 += fmaxf(acc[mt][n8][0] + bias0, 0.f);
                s1 += fmaxf(acc[mt][n8][1] + bias1, 0.f);
            }
            if (rr + 8 < len) {
                s0 += fmaxf(acc[mt][n8][2] + bias0, 0.f);
                s1 += fmaxf(acc[mt][n8][3] + bias1, 0.f);
            }
        }
#pragma unroll
        for (int o = 4; o < 32; o <<= 1) {
            s0 += __shfl_xor_sync(0xffffffffu, s0, o);
            s1 += __shfl_xor_sync(0xffffffffu, s1, o);
        }
        if (lane < 4) {
            part[wm * 128 + c0] = s0;
            part[wm * 128 + c0 + 1] = s1;
        }
    }
    __syncthreads();
    if (tid < 128) {
        float v = part[tid] + part[128 + tid] + part[256 + tid] + part[384 + tid];
        g_part[((size_t)tt * B_SZ + b) * HID + nt * BN + tid] = v;
    }
}

// ---------------- tail stage 1: per-(batch, 256-col slice) pool + W2 dot ----------------
__global__ void __launch_bounds__(256) pool_dot_kernel(const int* __restrict__ tl,
                                                       const float* __restrict__ W2) {
    __shared__ float red[16];  // 8 warps x 2 tags
    const int b = blockIdx.x, sl = blockIdx.y;
    const int tid = threadIdx.x, lane = tid & 31, wid = tid >> 5;
    const int len = tl[b];
    const int ntt = (len + BM - 1) >> 7;
    const float inv = 1.f / (float)len;
    const int hcol = sl * 256 + tid;

    float s = 0.f;
    for (int t = 0; t < ntt; t++)
        s += g_part[((size_t)t * B_SZ + b) * HID + hcol];
    float v = s * inv;
    float s0 = v * W2[hcol];
    float s1 = v * W2[HID + hcol];
#pragma unroll
    for (int o = 16; o > 0; o >>= 1) {
        s0 += __shfl_xor_sync(0xffffffffu, s0, o);
        s1 += __shfl_xor_sync(0xffffffffu, s1, o);
    }
    if (lane == 0) { red[wid * 2] = s0; red[wid * 2 + 1] = s1; }
    __syncthreads();
    if (tid < 2) {
        float t = 0.f;
#pragma unroll
        for (int w = 0; w < 8; w++) t += red[w * 2 + tid];
        g_red[(b * 8 + sl) * 2 + tid] = t;
    }
}

// ---------------- tail stage 2: fold 8 slices per (b, tag), add bias ----------------
__global__ void __launch_bounds__(64) score_final_kernel(const float* __restrict__ b2,
                                                         float* __restrict__ out) {
    int idx = threadIdx.x;             // 64 = 32 b x 2 tags
    int b = idx >> 1, tag = idx & 1;
    float s = 0.f;
#pragma unroll
    for (int sl = 0; sl < 8; sl++) s += g_red[(b * 8 + sl) * 2 + tag];
    out[b * 2 + tag] = s + b2[tag];
}

// ---------------- launch ----------------
extern "C" void kernel_launch(void* const* d_in, const int* in_sizes, int n_in,
                              void* d_out, int out_size) {
    const float* h  = (const float*)d_in[0];
    const int*   tl = (const int*)d_in[1];
    const float* W1 = (const float*)d_in[2];
    const float* b1 = (const float*)d_in[3];
    const float* W2 = (const float*)d_in[4];
    const float* b2 = (const float*)d_in[5];
    float* out = (float*)d_out;

    static bool attr_set = false;
    if (!attr_set) {
        cudaFuncSetAttribute(gemm_kernel,
                             cudaFuncAttributeMaxDynamicSharedMemorySize, SMEM_TOTAL);
        attr_set = true;
    }

    cvt_h_kernel<<<(B_SZ * T_SZ * DIN / 16) / 256, 256>>>((const float4*)h, tl);
    cvt_w1_kernel<<<(HID * DIN / 8) / 256, 256>>>((const float4*)W1);
    gemm_kernel<<<dim3(HID / BN, T_SZ / BM, B_SZ), 256, SMEM_TOTAL>>>(tl, b1);
    pool_dot_kernel<<<dim3(B_SZ, 8), 256>>>(tl, W2);
    score_final_kernel<<<1, 64>>>(b2, out);
}